// round 12
// baseline (speedup 1.0000x reference)
#include <cuda_runtime.h>
#include <stdint.h>

// HT2SPHERE: out[bc, s] = sum over votes v with sph[v]==s of x[bc, ht[v]] * w[v]
// Counting-sort votes by sphere bin, transpose x to channel-contiguous layout
// (each vote's 256-channel column = one coalesced 1KB L2-resident read), then
// one atomic-free 64-thread slice per segment accumulates in registers and
// writes each output element exactly once.

#define S_BINS 16384
#define HW     16384
#define BC     256
#define MAXV   2097152

// Scratch (static __device__ — no allocation anywhere).
__device__ float g_xT[(size_t)HW * BC];      // 16 MB transposed input
__device__ uint2 g_votes[MAXV];              // binned (weight_bits, ht) pairs
__device__ int   g_counts[S_BINS];
__device__ int   g_start[S_BINS + 1];
__device__ int   g_cursor[S_BINS];

__global__ void zero_counts_k() {
    int i = blockIdx.x * blockDim.x + threadIdx.x;
    if (i < S_BINS) g_counts[i] = 0;
}

// x: (BC, HW) row-major -> g_xT: (HW, BC) row-major. Tiled 32x32 transpose.
__global__ void transpose_k(const float* __restrict__ x) {
    __shared__ float tile[32][33];
    int col0 = blockIdx.x * 32;   // hw
    int row0 = blockIdx.y * 32;   // bc
    int tx = threadIdx.x, ty = threadIdx.y;
#pragma unroll
    for (int j = 0; j < 32; j += 8)
        tile[ty + j][tx] = x[(size_t)(row0 + ty + j) * HW + col0 + tx];
    __syncthreads();
#pragma unroll
    for (int j = 0; j < 32; j += 8)
        g_xT[(size_t)(col0 + ty + j) * BC + row0 + tx] = tile[tx][ty + j];
}

__global__ void hist_k(const float* __restrict__ vm, int V) {
    int i = blockIdx.x * blockDim.x + threadIdx.x;
    if (i < V) {
        int s = (int)vm[(size_t)i * 3 + 2];
        atomicAdd(&g_counts[s], 1);
    }
}

// Exclusive scan of 16384 bin counts. One CTA, 512 threads x 32 bins each.
__global__ void scan_k() {
    __shared__ int wsum[16];
    int t = threadIdx.x;            // 0..511
    int base = t * 32;
    int local[32];
    int sum = 0;
#pragma unroll
    for (int j = 0; j < 32; j++) { local[j] = sum; sum += g_counts[base + j]; }
    int lane = t & 31, wid = t >> 5;
    int v = sum;
#pragma unroll
    for (int o = 1; o < 32; o <<= 1) {
        int n = __shfl_up_sync(0xffffffffu, v, o);
        if (lane >= o) v += n;
    }
    if (lane == 31) wsum[wid] = v;
    __syncthreads();
    if (wid == 0) {
        int w = (lane < 16) ? wsum[lane] : 0;
#pragma unroll
        for (int o = 1; o < 16; o <<= 1) {
            int n = __shfl_up_sync(0xffffffffu, w, o);
            if (lane >= o) w += n;
        }
        if (lane < 16) wsum[lane] = w;
    }
    __syncthreads();
    int excl = v - sum + (wid > 0 ? wsum[wid - 1] : 0);
#pragma unroll
    for (int j = 0; j < 32; j++) {
        int st = excl + local[j];
        g_start[base + j]  = st;
        g_cursor[base + j] = st;
    }
    if (t == 511) g_start[S_BINS] = excl + sum;
}

__global__ void scatter_k(const float* __restrict__ vm, int V) {
    int i = blockIdx.x * blockDim.x + threadIdx.x;
    if (i < V) {
        float h = vm[(size_t)i * 3 + 0];
        float w = vm[(size_t)i * 3 + 1];
        float s = vm[(size_t)i * 3 + 2];
        int pos = atomicAdd(&g_cursor[(int)s], 1);
        g_votes[pos] = make_uint2(__float_as_uint(w), (unsigned)(int)h);
    }
}

// One 64-thread slice per segment (4 segments per 256-thread CTA).
// Each thread owns 4 channels (one float4 of an xT row), accumulates in
// registers, writes its 4 output elements exactly once. Atomic-free.
// Software-pipelined to depth 2 so two vote+column loads are in flight.
__global__ void __launch_bounds__(256) gather_k(float* __restrict__ out) {
    int seg = blockIdx.x * 4 + (threadIdx.x >> 6);
    int l   = threadIdx.x & 63;
    const float4* __restrict__ xT4   = reinterpret_cast<const float4*>(g_xT);
    const uint2*  __restrict__ votes = g_votes;
    int i = __ldg(&g_start[seg]);
    int e = __ldg(&g_start[seg + 1]);
    int n = e - i;
    float ax = 0.f, ay = 0.f, az = 0.f, aw = 0.f;

    uint2  p0, p1;
    float4 v0, v1;
    if (n > 0) { p0 = __ldg(&votes[i]);     v0 = __ldg(&xT4[(size_t)p0.y * 64 + l]); }
    if (n > 1) { p1 = __ldg(&votes[i + 1]); v1 = __ldg(&xT4[(size_t)p1.y * 64 + l]); }

    int k = i + 2;
    // steady state: consume slot0, refill two ahead; rotate slots.
    while (k < e) {
        uint2  pn = __ldg(&votes[k]);
        float4 vn = __ldg(&xT4[(size_t)pn.y * 64 + l]);
        float w0 = __uint_as_float(p0.x);
        ax = fmaf(v0.x, w0, ax); ay = fmaf(v0.y, w0, ay);
        az = fmaf(v0.z, w0, az); aw = fmaf(v0.w, w0, aw);
        p0 = p1; v0 = v1;
        p1 = pn; v1 = vn;
        ++k;
    }
    if (n > 0) {
        float w0 = __uint_as_float(p0.x);
        ax = fmaf(v0.x, w0, ax); ay = fmaf(v0.y, w0, ay);
        az = fmaf(v0.z, w0, az); aw = fmaf(v0.w, w0, aw);
    }
    if (n > 1) {
        float w1 = __uint_as_float(p1.x);
        ax = fmaf(v1.x, w1, ax); ay = fmaf(v1.y, w1, ay);
        az = fmaf(v1.z, w1, az); aw = fmaf(v1.w, w1, aw);
    }

    int c0 = l * 4;
    out[(size_t)(c0 + 0) * S_BINS + seg] = ax;
    out[(size_t)(c0 + 1) * S_BINS + seg] = ay;
    out[(size_t)(c0 + 2) * S_BINS + seg] = az;
    out[(size_t)(c0 + 3) * S_BINS + seg] = aw;
}

extern "C" void kernel_launch(void* const* d_in, const int* in_sizes, int n_in,
                              void* d_out, int out_size) {
    const float* x  = nullptr;
    const float* vm = nullptr;
    int V = 0;
    // Identify inputs by element count: x = 4*64*128*128 = 4194304 (not
    // divisible by 3); vote_mapping = 3*V. sphere_size scalar matches neither.
    for (int i = 0; i < n_in; i++) {
        if (in_sizes[i] == BC * HW && !x) {
            x = (const float*)d_in[i];
        } else if (in_sizes[i] >= 3 && in_sizes[i] % 3 == 0) {
            if (!vm || in_sizes[i] / 3 > V) { vm = (const float*)d_in[i]; V = in_sizes[i] / 3; }
        }
    }
    if (!x)  x = (const float*)d_in[0];
    if (!vm) { vm = (const float*)d_in[1]; V = in_sizes[1] / 3; }
    if (V > MAXV) V = MAXV;
    if (V < 0)    V = 0;

    float* out = (float*)d_out;

    zero_counts_k<<<(S_BINS + 1023) / 1024, 1024>>>();
    transpose_k<<<dim3(HW / 32, BC / 32), dim3(32, 8)>>>(x);
    hist_k<<<(V + 255) / 256, 256>>>(vm, V);
    scan_k<<<1, 512>>>();
    scatter_k<<<(V + 255) / 256, 256>>>(vm, V);
    gather_k<<<S_BINS / 4, 256>>>(out);
}